// round 3
// baseline (speedup 1.0000x reference)
#include <cuda_runtime.h>

#define BB 8
#define CI 128
#define MC 64
#define HH 64
#define WW 64
#define NH 128
#define NW 128

// Scratch (allocation-free per harness rules)
__device__ float g_m[BB * MC * HH * WW];      // compressed features
__device__ float g_ker[BB * 25 * NH * NW];    // softmax kernels
__device__ float g_ew2[128 * 9 * 64];         // encoder weights [o][tap][c], o padded to 128

typedef unsigned long long u64;

__device__ __forceinline__ u64 pk2(float lo, float hi) {
    u64 r; asm("mov.b64 %0, {%1,%2};" : "=l"(r) : "f"(lo), "f"(hi)); return r;
}
__device__ __forceinline__ float2 upk2(u64 v) {
    float2 f; asm("mov.b64 {%0,%1}, %2;" : "=f"(f.x), "=f"(f.y) : "l"(v)); return f;
}
__device__ __forceinline__ void fma2(u64 &acc, u64 a, u64 b) {
    asm("fma.rn.f32x2 %0, %1, %2, %0;" : "+l"(acc) : "l"(a), "l"(b));
}

// ---------------------------------------------------------------------------
// Prep: transpose encoder weights (o,c,3,3) -> [o][tap][c], zero-pad o to 128
// ---------------------------------------------------------------------------
__global__ __launch_bounds__(256)
void k_prep(const float* __restrict__ ew) {
    int idx = blockIdx.x * 256 + threadIdx.x;   // over 128*9*64 = 73728
    if (idx >= 128 * 9 * 64) return;
    int c = idx & 63, tap = (idx >> 6) % 9, o = idx / 576;
    g_ew2[idx] = (o < 100) ? ew[o * 576 + c * 9 + tap] : 0.f;
}

// ---------------------------------------------------------------------------
// Kernel 1: 1x1 compress conv. block=(h,b), 256 thr.
// x row -> smem [w][c] (XOR-swizzled quads), weights -> smem [m][c].
// Thread: 16 m-channels for one w; weights via broadcast LDS.128.
// ---------------------------------------------------------------------------
extern __shared__ float sm1[];
__global__ __launch_bounds__(256)
void k_compress(const float* __restrict__ x, const float* __restrict__ cw,
                const float* __restrict__ cb) {
    float* xs = sm1;              // 64*128 floats, swizzled [w][c]
    float* ws = sm1 + 64 * 128;   // 64*128 floats, plain [m][c]
    const int h = blockIdx.x, b = blockIdx.y, tid = threadIdx.x;
    const float* xb = x + ((size_t)b * CI * HH + h) * WW;

    // stage x: per (c, w-quad) read float4 from gmem, scatter with swizzle
    for (int idx = tid; idx < CI * 16; idx += 256) {
        int w0 = (idx & 15) * 4, c = idx >> 4;
        float4 v = *reinterpret_cast<const float4*>(xb + (size_t)c * HH * WW + w0);
        int cq = c >> 2, cl = c & 3;
        float vv[4] = {v.x, v.y, v.z, v.w};
        #pragma unroll
        for (int k = 0; k < 4; k++) {
            int w = w0 + k;
            xs[(w << 7) + ((cq ^ (w & 7)) << 2) + cl] = vv[k];
        }
    }
    // stage weights (vectorized)
    for (int idx = tid; idx < MC * CI / 4; idx += 256)
        reinterpret_cast<float4*>(ws)[idx] = reinterpret_cast<const float4*>(cw)[idx];
    __syncthreads();

    const int w = tid & 63, mt = tid >> 6;   // mt: 0..3 -> 16 m each
    u64 acc[16];
    #pragma unroll
    for (int i = 0; i < 16; i++) acc[i] = 0;
    const float* xrow = xs + (w << 7);
    const float* wb = ws + mt * 16 * CI;
    const int wx = w & 7;
    #pragma unroll
    for (int cq = 0; cq < 32; cq++) {
        float4 xq = *reinterpret_cast<const float4*>(xrow + ((cq ^ wx) << 2));
        u64 xlo = pk2(xq.x, xq.y), xhi = pk2(xq.z, xq.w);
        #pragma unroll
        for (int mm = 0; mm < 16; mm++) {
            float4 wq = *reinterpret_cast<const float4*>(wb + mm * CI + (cq << 2));
            fma2(acc[mm], xlo, pk2(wq.x, wq.y));
            fma2(acc[mm], xhi, pk2(wq.z, wq.w));
        }
    }
    #pragma unroll
    for (int mm = 0; mm < 16; mm++) {
        int m = mt * 16 + mm;
        float2 r = upk2(acc[mm]);
        g_m[(((size_t)b * MC + m) * HH + h) * WW + w] = r.x + r.y + cb[m];
    }
}

// ---------------------------------------------------------------------------
// Kernel 2: 3x3 encoder conv (64->100) + bias + pixel-shuffle + softmax(25).
// block=(h,b), 256 thr. m halo rows in smem (c-minor, swizzled). Weights in
// smem chunks of 32 o. Warp = (w-half, 8-o tile); all hot-loop operands LDS.
// ---------------------------------------------------------------------------
extern __shared__ float sm2[];
__global__ __launch_bounds__(256)
void k_encoder(const float* __restrict__ eb) {
    float* m_s = sm2;                      // 3*66*64 = 12672 floats
    float* wsm = sm2 + 12672;              // 32*576  = 18432 floats
    float* kt  = sm2 + 12672 + 18432;      // 100*64  = 6400 floats
    const int h = blockIdx.x, b = blockIdx.y, tid = threadIdx.x;

    // stage m halo: [r][iw][c] swizzled, zero-padded borders
    for (int idx = tid; idx < 3 * 66 * 64; idx += 256) {
        int iw = idx % 66; int t2 = idx / 66; int r = t2 % 3; int c = t2 / 3;
        int hh = h + r - 1, ww = iw - 1;
        float v = 0.f;
        if ((unsigned)hh < HH && (unsigned)ww < WW)
            v = g_m[(((size_t)b * MC + c) * HH + hh) * WW + ww];
        int cq = c >> 2, cl = c & 3;
        m_s[((r * 66 + iw) << 6) + ((cq ^ (iw & 7)) << 2) + cl] = v;
    }

    const int wid = tid >> 5, lane = tid & 31;
    const int whalf = wid & 1, otile = wid >> 1;   // otile 0..3
    const int w = whalf * 32 + lane;

    for (int oc = 0; oc < 4; oc++) {
        __syncthreads();
        for (int idx = tid; idx < 32 * 576 / 4; idx += 256)
            reinterpret_cast<float4*>(wsm)[idx] =
                reinterpret_cast<const float4*>(g_ew2 + oc * 32 * 576)[idx];
        __syncthreads();

        const int ob = otile * 8;
        u64 acc[8];
        #pragma unroll
        for (int oo = 0; oo < 8; oo++) {
            int o = oc * 32 + ob + oo;
            acc[oo] = pk2(o < 100 ? __ldg(eb + o) : 0.f, 0.f);
        }
        #pragma unroll 1
        for (int r = 0; r < 3; r++) {
            #pragma unroll 1
            for (int s = 0; s < 3; s++) {
                const float* xrow = m_s + ((r * 66 + w + s) << 6);
                const int ixw = (w + s) & 7;
                const float* wt = wsm + ((ob * 9 + r * 3 + s) << 6);
                #pragma unroll
                for (int cq = 0; cq < 16; cq++) {
                    float4 xq = *reinterpret_cast<const float4*>(xrow + ((cq ^ ixw) << 2));
                    u64 xlo = pk2(xq.x, xq.y), xhi = pk2(xq.z, xq.w);
                    #pragma unroll
                    for (int oo = 0; oo < 8; oo++) {
                        float4 wq = *reinterpret_cast<const float4*>(
                            wt + ((oo * 9) << 6) + (cq << 2));
                        fma2(acc[oo], xlo, pk2(wq.x, wq.y));
                        fma2(acc[oo], xhi, pk2(wq.z, wq.w));
                    }
                }
            }
        }
        #pragma unroll
        for (int oo = 0; oo < 8; oo++) {
            int o = oc * 32 + ob + oo;
            if (o < 100) { float2 r2 = upk2(acc[oo]); kt[o * 64 + w] = r2.x + r2.y; }
        }
    }
    __syncthreads();

    // softmax over 25 taps; channel n = t*4 + sh*2 + sw
    {
        int sub = tid >> 6, w2 = tid & 63;
        int sh = sub >> 1, sw = sub & 1;
        float v[25]; float mx = -1e30f;
        #pragma unroll
        for (int t = 0; t < 25; t++) { v[t] = kt[(t * 4 + sub) * 64 + w2]; mx = fmaxf(mx, v[t]); }
        float ssum = 0.f;
        #pragma unroll
        for (int t = 0; t < 25; t++) { v[t] = __expf(v[t] - mx); ssum += v[t]; }
        float inv = 1.f / ssum;
        int oh = 2 * h + sh, ow = 2 * w2 + sw;
        #pragma unroll
        for (int t = 0; t < 25; t++)
            g_ker[(((size_t)b * 25 + t) * NH + oh) * NW + ow] = v[t] * inv;
    }
}

// ---------------------------------------------------------------------------
// Kernel 3: content-aware reassembly. block=(h,b) covers BOTH output rows
// (2h, 2h+1); thread = (w, c-oct) covers ow-pair (2w, 2w+1) so each x quad
// feeds 8 fma2 (2 oh x 2 ow x 2 c-pairs).
// ---------------------------------------------------------------------------
extern __shared__ float sm3[];
__global__ __launch_bounds__(256)
void k_carafe(const float* __restrict__ x, float* __restrict__ out) {
    float* ker_s = sm3;           // [t][p][128] = 6400 floats
    float* x_s   = sm3 + 6400;    // 5*68*32 = 10880 floats, swizzled
    const int h = blockIdx.x, b = blockIdx.y, tid = threadIdx.x;

    for (int idx = tid; idx < 25 * 2 * 128; idx += 256) {
        int ow = idx & 127; int t2 = idx >> 7; int p = t2 & 1; int t = t2 >> 1;
        ker_s[idx] = g_ker[(((size_t)b * 25 + t) * NH + 2 * h + p) * NW + ow];
    }
    const int w = tid & 63, co = tid >> 6;   // co: 0..3 -> 8 channels

    for (int c0 = 0; c0 < CI; c0 += 32) {
        __syncthreads();
        for (int idx = tid; idx < 5 * 68 * 32; idx += 256) {
            int iw = idx % 68; int t2 = idx / 68; int i = t2 % 5; int cc = t2 / 5;
            int row = h + i - 2, col = iw - 2;
            float v = 0.f;
            if ((unsigned)row < HH && (unsigned)col < WW)
                v = x[(((size_t)b * CI + c0 + cc) * HH + row) * WW + col];
            int cq = cc >> 2, cl = cc & 3;
            x_s[((i * 68 + iw) << 5) + ((cq ^ (iw & 7)) << 2) + cl] = v;
        }
        __syncthreads();

        u64 acc[4][4];   // [p*2+q][c-pair]
        #pragma unroll
        for (int a = 0; a < 4; a++)
            #pragma unroll
            for (int p = 0; p < 4; p++) acc[a][p] = 0;

        #pragma unroll 1
        for (int i = 0; i < 5; i++) {
            #pragma unroll
            for (int j = 0; j < 5; j++) {
                int t = i * 5 + j;
                int iw = w + j;
                const float* xr = x_s + ((i * 68 + iw) << 5);
                int sw8 = iw & 7;
                float4 xa = *reinterpret_cast<const float4*>(xr + (((co * 2) ^ sw8) << 2));
                float4 xc = *reinterpret_cast<const float4*>(xr + (((co * 2 + 1) ^ sw8) << 2));
                u64 X0 = pk2(xa.x, xa.y), X1 = pk2(xa.z, xa.w);
                u64 X2 = pk2(xc.x, xc.y), X3 = pk2(xc.z, xc.w);
                float2 k0 = *reinterpret_cast<const float2*>(ker_s + (t * 2 + 0) * 128 + 2 * w);
                float2 k1 = *reinterpret_cast<const float2*>(ker_s + (t * 2 + 1) * 128 + 2 * w);
                u64 K00 = pk2(k0.x, k0.x), K01 = pk2(k0.y, k0.y);
                u64 K10 = pk2(k1.x, k1.x), K11 = pk2(k1.y, k1.y);
                fma2(acc[0][0], X0, K00); fma2(acc[0][1], X1, K00);
                fma2(acc[0][2], X2, K00); fma2(acc[0][3], X3, K00);
                fma2(acc[1][0], X0, K01); fma2(acc[1][1], X1, K01);
                fma2(acc[1][2], X2, K01); fma2(acc[1][3], X3, K01);
                fma2(acc[2][0], X0, K10); fma2(acc[2][1], X1, K10);
                fma2(acc[2][2], X2, K10); fma2(acc[2][3], X3, K10);
                fma2(acc[3][0], X0, K11); fma2(acc[3][1], X1, K11);
                fma2(acc[3][2], X2, K11); fma2(acc[3][3], X3, K11);
            }
        }
        // writeback: STG.64 over ow-pair per (channel, oh)
        #pragma unroll
        for (int p = 0; p < 2; p++) {
            #pragma unroll
            for (int cp = 0; cp < 4; cp++) {
                float2 rA = upk2(acc[p * 2 + 0][cp]);   // q=0: channels (c, c+1)
                float2 rB = upk2(acc[p * 2 + 1][cp]);   // q=1
                int c = c0 + co * 8 + cp * 2;
                size_t base = (((size_t)b * CI + c) * NH + 2 * h + p) * NW + 2 * w;
                *reinterpret_cast<float2*>(out + base) = make_float2(rA.x, rB.x);
                *reinterpret_cast<float2*>(out + base + (size_t)NH * NW) = make_float2(rA.y, rB.y);
            }
        }
    }
}

// ---------------------------------------------------------------------------
extern "C" void kernel_launch(void* const* d_in, const int* in_sizes, int n_in,
                              void* d_out, int out_size) {
    const float* x  = (const float*)d_in[0];
    const float* cw = (const float*)d_in[1];
    const float* cb = (const float*)d_in[2];
    const float* ew = (const float*)d_in[3];
    const float* eb = (const float*)d_in[4];
    float* out = (float*)d_out;

    static int inited = 0;
    if (!inited) {
        cudaFuncSetAttribute(k_compress, cudaFuncAttributeMaxDynamicSharedMemorySize, 65536);
        cudaFuncSetAttribute(k_encoder,  cudaFuncAttributeMaxDynamicSharedMemorySize, 150016);
        cudaFuncSetAttribute(k_carafe,   cudaFuncAttributeMaxDynamicSharedMemorySize, 69120);
        inited = 1;
    }

    k_prep<<<288, 256>>>(ew);
    k_compress<<<dim3(HH, BB), 256, 65536>>>(x, cw, cb);
    k_encoder<<<dim3(HH, BB), 256, 150016>>>(eb);
    k_carafe<<<dim3(HH, BB), 256, 69120>>>(x, out);
}

// round 4
// speedup vs baseline: 2.0409x; 2.0409x over previous
#include <cuda_runtime.h>

#define BB 8
#define CI 128
#define MC 64
#define HH 64
#define WW 64
#define NH 128
#define NW 128
#define OP 112   // encoder outputs padded 100 -> 112 (14 o-tiles of 8)

// Scratch (allocation-free per harness rules)
__device__ float g_m[BB * MC * HH * WW];                 // compressed features
__device__ float g_ker[BB * 25 * NH * NW];               // softmax kernels
__device__ __align__(16) float g_ew2t[MC * 9 * OP];      // weights [c][tap][o]
__device__ __align__(16) float g_cw2[CI * MC];           // compress weights [c][m]

typedef unsigned long long u64;

__device__ __forceinline__ u64 pk2(float lo, float hi) {
    u64 r; asm("mov.b64 %0, {%1,%2};" : "=l"(r) : "f"(lo), "f"(hi)); return r;
}
__device__ __forceinline__ float2 upk2(u64 v) {
    float2 f; asm("mov.b64 {%0,%1}, %2;" : "=f"(f.x), "=f"(f.y) : "l"(v)); return f;
}
__device__ __forceinline__ void fma2(u64 &acc, u64 a, u64 b) {
    asm("fma.rn.f32x2 %0, %1, %2, %0;" : "+l"(acc) : "l"(a), "l"(b));
}
__device__ __forceinline__ u64 ld2(const float* p) {
    return *reinterpret_cast<const u64*>(p);
}

// ---------------------------------------------------------------------------
// Prep: weight transposes.  g_ew2t[c][tap][o] (o zero-padded to 112),
// g_cw2[c][m].
// ---------------------------------------------------------------------------
__global__ __launch_bounds__(256)
void k_prep(const float* __restrict__ ew, const float* __restrict__ cw) {
    int idx = blockIdx.x * 256 + threadIdx.x;
    const int n1 = MC * 9 * OP;          // 64512
    if (idx < n1) {
        int c = idx / (9 * OP);
        int rem = idx - c * 9 * OP;
        int tap = rem / OP, o = rem - tap * OP;
        g_ew2t[idx] = (o < 100) ? ew[o * 576 + c * 9 + tap] : 0.f;
    } else if (idx < n1 + CI * MC) {
        int j = idx - n1;
        int c = j >> 6, m = j & 63;
        g_cw2[j] = cw[m * CI + c];
    }
}

// ---------------------------------------------------------------------------
// Kernel 1: 1x1 compress conv.  block=(h-pair, b), 128 thr, 1 wave.
// xs [c][r][68] padded rows; thread = (m-tile 8, row, w-tile 8).
// Per c: 4 LDS.64 x-pairs + 8 scalar W + 8 splats + 32 fma2  (64 B/fma2).
// ---------------------------------------------------------------------------
extern __shared__ float sm1[];
__global__ __launch_bounds__(128)
void k_compress(const float* __restrict__ x, const float* __restrict__ cb) {
    float* xs = sm1;                 // CI*2*68 floats
    float* ws = sm1 + CI * 2 * 68;   // CI*64 floats
    const int hb = blockIdx.x, b = blockIdx.y, tid = threadIdx.x;

    const float4* x4 = reinterpret_cast<const float4*>(x) + (size_t)b * (CI * HH * WW / 4);
    for (int idx = tid; idx < CI * 2 * 16; idx += 128) {
        int q = idx & 15, r = (idx >> 4) & 1, c = idx >> 5;
        float4 v = x4[(c * HH + 2 * hb + r) * 16 + q];
        *reinterpret_cast<float4*>(xs + (c * 2 + r) * 68 + q * 4) = v;
    }
    for (int idx = tid; idx < CI * MC / 4; idx += 128)
        reinterpret_cast<float4*>(ws)[idx] = reinterpret_cast<const float4*>(g_cw2)[idx];
    __syncthreads();

    const int mt = tid >> 4, wt = tid & 15;
    const int r = wt >> 3, w0 = (wt & 7) * 8, m0 = mt * 8;

    u64 acc[4][8];
    #pragma unroll
    for (int m = 0; m < 8; m++) {
        float bv = cb[m0 + m];
        u64 bb = pk2(bv, bv);
        #pragma unroll
        for (int wp = 0; wp < 4; wp++) acc[wp][m] = (wp == 0) ? bb : 0;
    }
    #pragma unroll 2
    for (int c = 0; c < CI; c++) {
        const float* xr = xs + (c * 2 + r) * 68 + w0;
        u64 X0 = ld2(xr), X1 = ld2(xr + 2), X2 = ld2(xr + 4), X3 = ld2(xr + 6);
        const float* wr = ws + c * 64 + m0;
        #pragma unroll
        for (int m = 0; m < 8; m++) {
            float wv = wr[m];
            u64 W = pk2(wv, wv);
            fma2(acc[0][m], X0, W); fma2(acc[1][m], X1, W);
            fma2(acc[2][m], X2, W); fma2(acc[3][m], X3, W);
        }
    }
    // wp>0 accs missed the bias; add via pair-merge at writeback? No: bias was
    // only in wp==0. Add bias to wp 1..3 here (cheap, 24 adds).
    #pragma unroll
    for (int m = 0; m < 8; m++) {
        float bv = cb[m0 + m];
        #pragma unroll
        for (int wp = 1; wp < 4; wp++) {
            float2 v = upk2(acc[wp][m]);
            acc[wp][m] = pk2(v.x + bv, v.y + bv);
        }
    }
    #pragma unroll
    for (int m = 0; m < 8; m++)
        #pragma unroll
        for (int wp = 0; wp < 4; wp++) {
            float2 v = upk2(acc[wp][m]);
            *reinterpret_cast<float2*>(
                g_m + (((size_t)b * MC + m0 + m) * HH + 2 * hb + r) * WW + w0 + 2 * wp) = v;
        }
}

// ---------------------------------------------------------------------------
// Kernel 2: 3x3 encoder conv + bias + pixel-shuffle + softmax. block=(h,b),
// 112 thr (14 o-tiles x 8 w-tiles), 4 blocks/SM -> single wave.
// m chunk [8c][3r][72] (halo slots zeroed), W chunk [8c][9][112] o-minor.
// Per (c,r): 11-float x window to regs; per tap: 4 LDS.64 W-pairs + 8 splats
// + 32 fma2. kt aliases staging smem after compute.
// ---------------------------------------------------------------------------
extern __shared__ float sm2[];
__global__ __launch_bounds__(112, 4)
void k_encoder(const float* __restrict__ eb) {
    float* m_s = sm2;                 // 8*3*72 = 1728
    float* w_s = sm2 + 1728;          // 8*9*112 = 8064
    float* kt  = sm2;                 // alias, 112*64 = 7168
    const int h = blockIdx.x, b = blockIdx.y, tid = threadIdx.x;
    const int ot = tid >> 3, wt = tid & 7;
    const int o0 = ot * 8, w0 = wt * 8;

    u64 acc[4][8];
    #pragma unroll
    for (int j = 0; j < 4; j++) {
        int o = o0 + 2 * j;
        float b0 = (o < 100) ? __ldg(eb + o) : 0.f;
        float b1 = (o + 1 < 100) ? __ldg(eb + o + 1) : 0.f;
        u64 bb = pk2(b0, b1);
        #pragma unroll
        for (int k = 0; k < 8; k++) acc[j][k] = bb;
    }

    for (int cc0 = 0; cc0 < MC; cc0 += 8) {
        __syncthreads();
        for (int idx = tid; idx < 24 * 16; idx += 112) {
            int q = idx & 15, row = idx >> 4;       // row = c*3 + r
            int c = row / 3, r = row - c * 3;
            int hh = h + r - 1;
            float4 v = make_float4(0.f, 0.f, 0.f, 0.f);
            if ((unsigned)hh < HH)
                v = *reinterpret_cast<const float4*>(
                    g_m + (((size_t)b * MC + cc0 + c) * HH + hh) * WW + q * 4);
            *reinterpret_cast<float4*>(m_s + row * 72 + 4 + q * 4) = v;
        }
        for (int idx = tid; idx < 48; idx += 112) {
            int row = idx >> 1, e = idx & 1;
            *reinterpret_cast<float4*>(m_s + row * 72 + (e ? 68 : 0)) =
                make_float4(0.f, 0.f, 0.f, 0.f);
        }
        {
            const float4* wsrc = reinterpret_cast<const float4*>(g_ew2t + cc0 * 9 * OP);
            for (int idx = tid; idx < 8 * 9 * OP / 4; idx += 112)
                reinterpret_cast<float4*>(w_s)[idx] = wsrc[idx];
        }
        __syncthreads();

        #pragma unroll 1
        for (int c = 0; c < 8; c++) {
            #pragma unroll
            for (int r = 0; r < 3; r++) {
                const float* mr = m_s + (c * 3 + r) * 72 + w0;
                float xv[11];
                xv[0] = mr[3];
                float4 A = *reinterpret_cast<const float4*>(mr + 4);
                float4 Bv = *reinterpret_cast<const float4*>(mr + 8);
                float4 Cv = *reinterpret_cast<const float4*>(mr + 12);
                xv[1] = A.x; xv[2] = A.y; xv[3] = A.z; xv[4] = A.w;
                xv[5] = Bv.x; xv[6] = Bv.y; xv[7] = Bv.z; xv[8] = Bv.w;
                xv[9] = Cv.x; xv[10] = Cv.y;
                #pragma unroll
                for (int s = 0; s < 3; s++) {
                    const float* wr = w_s + (c * 9 + r * 3 + s) * OP + o0;
                    u64 W0 = ld2(wr), W1 = ld2(wr + 2), W2 = ld2(wr + 4), W3 = ld2(wr + 6);
                    #pragma unroll
                    for (int k = 0; k < 8; k++) {
                        u64 X = pk2(xv[k + s], xv[k + s]);
                        fma2(acc[0][k], X, W0);
                        fma2(acc[1][k], X, W1);
                        fma2(acc[2][k], X, W2);
                        fma2(acc[3][k], X, W3);
                    }
                }
            }
        }
    }
    __syncthreads();
    #pragma unroll
    for (int j = 0; j < 4; j++)
        #pragma unroll
        for (int k = 0; k < 8; k++) {
            float2 v = upk2(acc[j][k]);
            kt[(o0 + 2 * j) * 64 + w0 + k] = v.x;
            kt[(o0 + 2 * j + 1) * 64 + w0 + k] = v.y;
        }
    __syncthreads();

    for (int task = tid; task < 256; task += 112) {
        int sub = task >> 6, w2 = task & 63;
        int sh = sub >> 1, sw = sub & 1;
        float v[25]; float mx = -1e30f;
        #pragma unroll
        for (int t = 0; t < 25; t++) { v[t] = kt[(t * 4 + sub) * 64 + w2]; mx = fmaxf(mx, v[t]); }
        float ssum = 0.f;
        #pragma unroll
        for (int t = 0; t < 25; t++) { v[t] = __expf(v[t] - mx); ssum += v[t]; }
        float inv = 1.f / ssum;
        int oh = 2 * h + sh, ow = 2 * w2 + sw;
        #pragma unroll
        for (int t = 0; t < 25; t++)
            g_ker[(((size_t)b * 25 + t) * NH + oh) * NW + ow] = v[t] * inv;
    }
}

// ---------------------------------------------------------------------------
// Kernel 3: content-aware reassembly. block=(h,b) covers oh pair, all ow/c.
// x staged once: [c][i][72] padded rows (halo zeroed). Thread = (w, co).
// Per tap: 2 ld2 ker-pairs + 8 scalar x + 8 splats + 16 fma2; all immediate
// offsets. 4 register-resident channel chunks.
// ---------------------------------------------------------------------------
extern __shared__ float sm3[];
__global__ __launch_bounds__(256)
void k_carafe(const float* __restrict__ x, float* __restrict__ out) {
    float* ker_s = sm3;           // 50*128 = 6400
    float* x_s   = sm3 + 6400;    // 640*72 = 46080
    const int h = blockIdx.x, b = blockIdx.y, tid = threadIdx.x;

    for (int idx = tid; idx < 6400; idx += 256) {
        int ow = idx & 127, tp = idx >> 7;
        ker_s[idx] = g_ker[(((size_t)b * 25 + (tp >> 1)) * NH + 2 * h + (tp & 1)) * NW + ow];
    }
    for (int idx = tid; idx < 10240; idx += 256) {
        int q = idx & 15, row = idx >> 4;           // row = c*5 + i
        int c = row / 5, i = row - c * 5;
        int hh = h + i - 2;
        float4 v = make_float4(0.f, 0.f, 0.f, 0.f);
        if ((unsigned)hh < HH)
            v = *reinterpret_cast<const float4*>(
                x + (((size_t)b * CI + c) * HH + hh) * WW + q * 4);
        *reinterpret_cast<float4*>(x_s + row * 72 + 4 + q * 4) = v;
    }
    for (int idx = tid; idx < 1280; idx += 256) {
        int row = idx >> 1, e = idx & 1;
        *reinterpret_cast<float4*>(x_s + row * 72 + (e ? 68 : 0)) =
            make_float4(0.f, 0.f, 0.f, 0.f);
    }
    __syncthreads();

    const int w = tid & 63, co = tid >> 6;
    const float* kb = ker_s + 2 * w;

    #pragma unroll 1
    for (int c0 = 0; c0 < 4; c0++) {
        const float* xb = x_s + (size_t)(c0 * 32 + co * 8) * 360 + w + 2;
        u64 acc[2][8];
        #pragma unroll
        for (int p = 0; p < 2; p++)
            #pragma unroll
            for (int cc = 0; cc < 8; cc++) acc[p][cc] = 0;

        #pragma unroll
        for (int i = 0; i < 5; i++) {
            #pragma unroll
            for (int j = 0; j < 5; j++) {
                const int t = i * 5 + j;
                u64 K0 = ld2(kb + (2 * t) * 128);
                u64 K1 = ld2(kb + (2 * t + 1) * 128);
                #pragma unroll
                for (int cc = 0; cc < 8; cc++) {
                    float xv = xb[cc * 360 + i * 72 + j];
                    u64 X = pk2(xv, xv);
                    fma2(acc[0][cc], X, K0);
                    fma2(acc[1][cc], X, K1);
                }
            }
        }
        #pragma unroll
        for (int p = 0; p < 2; p++)
            #pragma unroll
            for (int cc = 0; cc < 8; cc++) {
                float2 v = upk2(acc[p][cc]);
                int ch = c0 * 32 + co * 8 + cc;
                *reinterpret_cast<float2*>(
                    out + (((size_t)b * CI + ch) * NH + 2 * h + p) * NW + 2 * w) = v;
            }
    }
}

// ---------------------------------------------------------------------------
extern "C" void kernel_launch(void* const* d_in, const int* in_sizes, int n_in,
                              void* d_out, int out_size) {
    const float* x  = (const float*)d_in[0];
    const float* cw = (const float*)d_in[1];
    const float* cb = (const float*)d_in[2];
    const float* ew = (const float*)d_in[3];
    const float* eb = (const float*)d_in[4];
    float* out = (float*)d_out;

    const int smem1 = (CI * 2 * 68 + CI * MC) * 4;     // 102400
    const int smem2 = (1728 + 8064) * 4;               // 39168
    const int smem3 = (6400 + 640 * 72) * 4;           // 209920
    cudaFuncSetAttribute(k_compress, cudaFuncAttributeMaxDynamicSharedMemorySize, smem1);
    cudaFuncSetAttribute(k_encoder,  cudaFuncAttributeMaxDynamicSharedMemorySize, smem2);
    cudaFuncSetAttribute(k_carafe,   cudaFuncAttributeMaxDynamicSharedMemorySize, smem3);

    k_prep<<<(MC * 9 * OP + CI * MC + 255) / 256, 256>>>(ew, cw);
    k_compress<<<dim3(HH / 2, BB), 128, smem1>>>(x, cb);
    k_encoder<<<dim3(HH, BB), 112, smem2>>>(eb);
    k_carafe<<<dim3(HH, BB), 256, smem3>>>(x, out);
}